// round 15
// baseline (speedup 1.0000x reference)
#include <cuda_runtime.h>
#include <cuda_fp16.h>
#include <math.h>

#define NPTS   8192
#define MPTS   8192
#define NB     16
#define WIDTH  32
#define NSPLIT 19
#define MAXJ   432   // ceil(8192/19) = 432 = 27*16 exactly
#define IBLK   256
#define REC    12    // x, y, z, w_h2(u32), bp_h2[8](u32)
#define PPW    4     // points per warp in setup (independent chains for ILP)

__device__ float g_packed[NPTS * REC];
__device__ __align__(16) float g_heg[NB];
__device__ float g_partial[(size_t)NSPLIT * MPTS * NB];

// ---- raw MUFU helpers ----
__device__ __forceinline__ float f_ex2(float x) {
    float r; asm("ex2.approx.f32 %0, %1;" : "=f"(r) : "f"(x)); return r;
}
__device__ __forceinline__ float f_lg2(float x) {
    float r; asm("lg2.approx.f32 %0, %1;" : "=f"(r) : "f"(x)); return r;
}
__device__ __forceinline__ float f_rcp(float x) {
    float r; asm("rcp.approx.f32 %0, %1;" : "=f"(r) : "f"(x)); return r;
}
__device__ __forceinline__ float fast_tanh(float a) {
    float u = f_ex2(2.885390081777927f * a);   // exp(2a)
    return fmaf(-2.0f, f_rcp(u + 1.0f), 1.0f);
}
__device__ __forceinline__ float fast_log_cosh(float t) {
    const float LN2 = 0.69314718055994531f;
    float a = fabsf(t);
    float v = f_ex2(-2.885390081777927f * a);  // exp(-2a)
    return fmaf(f_lg2(1.0f + v), LN2, a - LN2);
}

// Guaranteed single-op f16x2 exp2 on MUFU (two values per MUFU slot).
__device__ __forceinline__ unsigned h2ex2_raw(unsigned x) {
    unsigned r;
    asm("ex2.approx.f16x2 %0, %1;" : "=r"(r) : "r"(x));
    return r;
}

// Warp-per-point setup, 4 points per warp: four independent dependence
// chains interleave to hide LDG + MUFU + shfl-chain latency (the
// one-point version was latency-bound at ~11us regardless of math).
// Lane k owns hidden unit k; WIDTH->NB via 32 SHFL broadcasts
// (2 accumulators halve the serial chain); lane b<16 owns basis b.
__global__ void __launch_bounds__(256)
setup_kernel(const float* __restrict__ rho,
             const float* __restrict__ gamma,
             const float* __restrict__ coords,
             const float* __restrict__ weights,
             const float* __restrict__ w1,
             const float* __restrict__ b1,
             const float* __restrict__ w2,
             const float* __restrict__ b2) {
    __shared__ float s_w2[WIDTH * NB];
    int tid = threadIdx.x;
    for (int v = tid; v < WIDTH * NB; v += blockDim.x) s_w2[v] = w2[v];
    __syncthreads();

    int lane = tid & 31;
    int warp = tid >> 5;
    int jbase = blockIdx.x * (blockDim.x >> 5) + warp;   // 0..NPTS/PPW-1

    const float C     = 38.283120002509214f;   // 4*(3*pi^2)^(2/3)
    const float LOG2E = 1.44269504088896340f;
    const float LN2   = 0.69314718055994531f;
    const int   STRIDE = NPTS / PPW;           // 2048

    float w1l = w1[lane];
    float b1l = b1[lane];
    int bl = lane & (NB - 1);
    float b2l = b2[bl];

#pragma unroll
    for (int pp = 0; pp < PPW; pp++) {
        int j = jbase + pp * STRIDE;

        float r = rho[j];
        float l = f_lg2(r);
        float r83 = r * r * f_ex2(l * (2.0f / 3.0f));      // r^(8/3)
        float s2 = gamma[j] * f_rcp(C * r83);
        float x = f_lg2(s2 + 1e-4f) * LN2;                 // log(s2+eps)

        float h = fast_tanh(fmaf(x, w1l, b1l));

        float o0 = b2l, o1 = 0.0f;
#pragma unroll
        for (int k = 0; k < WIDTH; k += 2) {
            float hk0 = __shfl_sync(0xffffffffu, h, k);
            float hk1 = __shfl_sync(0xffffffffu, h, k + 1);
            o0 = fmaf(hk0, s_w2[k * NB + bl], o0);
            o1 = fmaf(hk1, s_w2[(k + 1) * NB + bl], o1);
        }
        float o = o0 + o1;

        float pref = 3.14159265358979323846f * f_ex2((l - 1.0f) * (2.0f / 3.0f));
        float bp = -pref * fast_log_cosh(o) * LOG2E;

        // pack channel pairs (2q, 2q+1) into half2
        float bpn = __shfl_down_sync(0xffffffffu, bp, 1);
        if (lane < NB && (lane & 1) == 0) {
            __half2 hh = __floats2half2_rn(bp, bpn);
            ((unsigned*)g_packed)[j * REC + 4 + (lane >> 1)] = *(unsigned*)&hh;
        }
        if (lane == 16) g_packed[j * REC + 0] = coords[j * 3 + 0];
        if (lane == 17) g_packed[j * REC + 1] = coords[j * 3 + 1];
        if (lane == 18) g_packed[j * REC + 2] = coords[j * 3 + 2];
        if (lane == 19) {
            __half2 wh = __float2half2_rn(weights[j] * r);
            ((unsigned*)g_packed)[j * REC + 3] = *(unsigned*)&wh;
        }
    }

    if (jbase == 0) {
        // heg_scale: field_embed at x = 0
        float h0 = fast_tanh(b1l);
        float q0 = b2l;
#pragma unroll
        for (int k = 0; k < WIDTH; k++) {
            float hk = __shfl_sync(0xffffffffu, h0, k);
            q0 = fmaf(hk, s_w2[k * NB + bl], q0);
        }
        if (lane < NB) {
            float lc = fast_log_cosh(q0);
            g_heg[lane] = lc * sqrtf(lc);                  // lc^1.5
        }
    }
}

// Grid (32, 19) = 608 blocks = 152 SMs x 4: perfectly balanced on GB300.
// Tile zero-padded to exactly MAXJ=432=27*16 records: the j-nest has
// constant trip counts (27 x 16), branch-free straight-line body.
// Zero records contribute exactly +0 (w=0), so padding is bit-identical.
__global__ void __launch_bounds__(IBLK)
main_kernel(const float* __restrict__ out_coords) {
    __shared__ float tile[MAXJ * REC];   // 20.7 KB

    int i = blockIdx.x * IBLK + threadIdx.x;
    int split = blockIdx.y;

    float ox = out_coords[i * 3 + 0];
    float oy = out_coords[i * 3 + 1];
    float oz = out_coords[i * 3 + 2];

    int jbeg = (split * NPTS) / NSPLIT;
    int jend = ((split + 1) * NPTS) / NSPLIT;
    int cnt = jend - jbeg;

    {
        const float4* src = (const float4*)(g_packed + (size_t)jbeg * REC);
        float4* dst = (float4*)tile;
        int nvec = cnt * (REC / 4);            // 3 float4 per j
        const int nvec_pad = MAXJ * (REC / 4); // fill remainder with zeros
        for (int v = threadIdx.x; v < nvec_pad; v += IBLK)
            dst[v] = (v < nvec) ? src[v]
                                : make_float4(0.0f, 0.0f, 0.0f, 0.0f);
    }
    __syncthreads();

    float acc[NB];
#pragma unroll
    for (int b = 0; b < NB; b++) acc[b] = 0.0f;

#pragma unroll 1
    for (int j0 = 0; j0 < MAXJ; j0 += 16) {
        // half2 partial accumulators (16 terms, each <=0.2: no overflow)
        __half2 hacc[8];
#pragma unroll
        for (int q = 0; q < 8; q++) hacc[q] = __float2half2_rn(0.0f);

#pragma unroll
        for (int jt = j0; jt < j0 + 16; ++jt) {
            const float* p = tile + jt * REC;
            float4 cw = *(const float4*)p;   // x, y, z, w_h2(bits)
            float dx = ox - cw.x;
            float dy = oy - cw.y;
            float dz = oz - cw.z;
            float d2 = fmaf(dx, dx, fmaf(dy, dy, dz * dz));
            __half2 d2h = __float2half2_rn(d2);      // one F2FP pack
            __half2 wh = *(__half2*)&cw.w;
            const __half2* bp = (const __half2*)(p + 4);
#pragma unroll
            for (int q = 0; q < 8; q++) {
                __half2 arg = __hmul2(bp[q], d2h);   // HMUL2 (fma pipe)
                unsigned eu = h2ex2_raw(*(unsigned*)&arg); // 1 MUFU, 2 exps
                hacc[q] = __hfma2(*(__half2*)&eu, wh, hacc[q]);
            }
        }
        // flush to f32
#pragma unroll
        for (int q = 0; q < 8; q++) {
            float2 f = __half22float2(hacc[q]);
            acc[2 * q + 0] += f.x;
            acc[2 * q + 1] += f.y;
        }
    }

    float* outp = g_partial + ((size_t)split * MPTS + i) * NB;
#pragma unroll
    for (int b = 0; b < NB; b++) outp[b] = acc[b];
}

// Vectorized reduce: one thread per 4 outputs, float4 loads across splits.
__global__ void reduce_kernel(float4* __restrict__ out4) {
    int t = blockIdx.x * blockDim.x + threadIdx.x;   // 0 .. MPTS*NB/4-1
    if (t >= MPTS * NB / 4) return;
    float4 s = make_float4(0.0f, 0.0f, 0.0f, 0.0f);
    const float4* part4 = (const float4*)g_partial;
    const int stride = MPTS * NB / 4;
#pragma unroll
    for (int sp = 0; sp < NSPLIT; sp++) {
        float4 v = part4[(size_t)sp * stride + t];
        s.x += v.x; s.y += v.y; s.z += v.z; s.w += v.w;
    }
    float4 hg = ((const float4*)g_heg)[t & 3];   // 4 consecutive channels
    s.x *= hg.x; s.y *= hg.y; s.z *= hg.z; s.w *= hg.w;
    out4[t] = s;
}

extern "C" void kernel_launch(void* const* d_in, const int* in_sizes, int n_in,
                              void* d_out, int out_size) {
    const float* rho        = (const float*)d_in[0];
    const float* gamma      = (const float*)d_in[1];
    const float* coords     = (const float*)d_in[2];
    const float* weights    = (const float*)d_in[3];
    const float* out_coords = (const float*)d_in[4];
    const float* w1         = (const float*)d_in[5];
    const float* b1         = (const float*)d_in[6];
    const float* w2         = (const float*)d_in[7];
    const float* b2         = (const float*)d_in[8];

    setup_kernel<<<NPTS / (8 * PPW), 256>>>(rho, gamma, coords, weights,
                                            w1, b1, w2, b2);
    dim3 grid(MPTS / IBLK, NSPLIT);
    main_kernel<<<grid, IBLK>>>(out_coords);
    reduce_kernel<<<(MPTS * NB / 4 + 255) / 256, 256>>>((float4*)d_out);
}

// round 16
// speedup vs baseline: 1.0061x; 1.0061x over previous
#include <cuda_runtime.h>
#include <cuda_fp16.h>
#include <math.h>

#define NPTS   8192
#define MPTS   8192
#define NB     16
#define WIDTH  32
#define NSPLIT 19
#define MAXJ   432   // ceil(8192/19) = 432 = 27*16 exactly
#define IBLK   256
#define REC    12    // x, y, z, w_h2(u32), bp_h2[8](u32)

__device__ float g_packed[NPTS * REC];
__device__ __align__(16) float g_heg[NB];
__device__ float g_partial[(size_t)NSPLIT * MPTS * NB];

// ---- raw MUFU helpers ----
__device__ __forceinline__ float f_ex2(float x) {
    float r; asm("ex2.approx.f32 %0, %1;" : "=f"(r) : "f"(x)); return r;
}
__device__ __forceinline__ float f_lg2(float x) {
    float r; asm("lg2.approx.f32 %0, %1;" : "=f"(r) : "f"(x)); return r;
}
__device__ __forceinline__ float f_rcp(float x) {
    float r; asm("rcp.approx.f32 %0, %1;" : "=f"(r) : "f"(x)); return r;
}
__device__ __forceinline__ float fast_tanh(float a) {
    float u = f_ex2(2.885390081777927f * a);   // exp(2a)
    return fmaf(-2.0f, f_rcp(u + 1.0f), 1.0f);
}
__device__ __forceinline__ float fast_log_cosh(float t) {
    const float LN2 = 0.69314718055994531f;
    float a = fabsf(t);
    float v = f_ex2(-2.885390081777927f * a);  // exp(-2a)
    return fmaf(f_lg2(1.0f + v), LN2, a - LN2);
}

// Guaranteed single-op f16x2 exp2 on MUFU (two values per MUFU slot).
__device__ __forceinline__ unsigned h2ex2_raw(unsigned x) {
    unsigned r;
    asm("ex2.approx.f16x2 %0, %1;" : "=r"(r) : "r"(x));
    return r;
}

// Warp-per-point setup (PPW=1: 8192 warps of TLP beats per-warp ILP —
// measured R14 vs R15). Lane k owns hidden unit k; WIDTH->NB via 32 SHFL
// broadcasts (2 accumulators halve the serial chain); lane b<16 owns basis b.
__global__ void __launch_bounds__(256)
setup_kernel(const float* __restrict__ rho,
             const float* __restrict__ gamma,
             const float* __restrict__ coords,
             const float* __restrict__ weights,
             const float* __restrict__ w1,
             const float* __restrict__ b1,
             const float* __restrict__ w2,
             const float* __restrict__ b2) {
    __shared__ float s_w2[WIDTH * NB];
    int tid = threadIdx.x;
    for (int v = tid; v < WIDTH * NB; v += blockDim.x) s_w2[v] = w2[v];
    __syncthreads();

    int lane = tid & 31;
    int warp = tid >> 5;
    int j = blockIdx.x * (blockDim.x >> 5) + warp;
    if (j >= NPTS) return;

    const float C     = 38.283120002509214f;   // 4*(3*pi^2)^(2/3)
    const float LOG2E = 1.44269504088896340f;
    const float LN2   = 0.69314718055994531f;

    float r = rho[j];
    float l = f_lg2(r);
    float r83 = r * r * f_ex2(l * (2.0f / 3.0f));          // r^(8/3)
    float s2 = gamma[j] * f_rcp(C * r83);
    float x = f_lg2(s2 + 1e-4f) * LN2;                     // log(s2+eps)

    float h = fast_tanh(fmaf(x, w1[lane], b1[lane]));

    int bl = lane & (NB - 1);
    float o0 = b2[bl], o1 = 0.0f;
#pragma unroll
    for (int k = 0; k < WIDTH; k += 2) {
        float hk0 = __shfl_sync(0xffffffffu, h, k);
        float hk1 = __shfl_sync(0xffffffffu, h, k + 1);
        o0 = fmaf(hk0, s_w2[k * NB + bl], o0);
        o1 = fmaf(hk1, s_w2[(k + 1) * NB + bl], o1);
    }
    float o = o0 + o1;

    float pref = 3.14159265358979323846f * f_ex2((l - 1.0f) * (2.0f / 3.0f));
    float bp = -pref * fast_log_cosh(o) * LOG2E;

    // pack channel pairs (2q, 2q+1) into half2
    float bpn = __shfl_down_sync(0xffffffffu, bp, 1);
    if (lane < NB && (lane & 1) == 0) {
        __half2 hh = __floats2half2_rn(bp, bpn);
        ((unsigned*)g_packed)[j * REC + 4 + (lane >> 1)] = *(unsigned*)&hh;
    }
    if (lane == 16) g_packed[j * REC + 0] = coords[j * 3 + 0];
    if (lane == 17) g_packed[j * REC + 1] = coords[j * 3 + 1];
    if (lane == 18) g_packed[j * REC + 2] = coords[j * 3 + 2];
    if (lane == 19) {
        __half2 wh = __float2half2_rn(weights[j] * r);
        ((unsigned*)g_packed)[j * REC + 3] = *(unsigned*)&wh;
    }

    if (j == 0) {
        float h0 = fast_tanh(b1[lane]);
        float q0 = b2[bl];
#pragma unroll
        for (int k = 0; k < WIDTH; k++) {
            float hk = __shfl_sync(0xffffffffu, h0, k);
            q0 = fmaf(hk, s_w2[k * NB + bl], q0);
        }
        if (lane < NB) {
            float lc = fast_log_cosh(q0);
            g_heg[lane] = lc * sqrtf(lc);                  // lc^1.5
        }
    }
}

// Grid (32, 19) = 608 blocks = 152 SMs x 4: perfectly balanced on GB300
// (152 = 8*19 forces NSPLIT=19 for balance). Tile zero-padded to exactly
// MAXJ=432=27*16 records: constant trip counts, branch-free body.
// Zero records contribute exactly +0 (w=0), so padding is bit-identical.
// All per-jt smem reads are LDS.128 (cw + two bp float4s).
__global__ void __launch_bounds__(IBLK)
main_kernel(const float* __restrict__ out_coords) {
    __shared__ float tile[MAXJ * REC];   // 20.7 KB

    int i = blockIdx.x * IBLK + threadIdx.x;
    int split = blockIdx.y;

    float ox = out_coords[i * 3 + 0];
    float oy = out_coords[i * 3 + 1];
    float oz = out_coords[i * 3 + 2];

    int jbeg = (split * NPTS) / NSPLIT;
    int jend = ((split + 1) * NPTS) / NSPLIT;
    int cnt = jend - jbeg;

    {
        const float4* src = (const float4*)(g_packed + (size_t)jbeg * REC);
        float4* dst = (float4*)tile;
        int nvec = cnt * (REC / 4);            // 3 float4 per j
        const int nvec_pad = MAXJ * (REC / 4); // fill remainder with zeros
        for (int v = threadIdx.x; v < nvec_pad; v += IBLK)
            dst[v] = (v < nvec) ? src[v]
                                : make_float4(0.0f, 0.0f, 0.0f, 0.0f);
    }
    __syncthreads();

    float acc[NB];
#pragma unroll
    for (int b = 0; b < NB; b++) acc[b] = 0.0f;

#pragma unroll 1
    for (int j0 = 0; j0 < MAXJ; j0 += 16) {
        // half2 partial accumulators (16 terms, each <=0.2: no overflow)
        __half2 hacc[8];
#pragma unroll
        for (int q = 0; q < 8; q++) hacc[q] = __float2half2_rn(0.0f);

#pragma unroll
        for (int jt = j0; jt < j0 + 16; ++jt) {
            const float4* p4 = (const float4*)(tile + jt * REC);
            float4 cw = p4[0];               // x, y, z, w_h2(bits)
            float4 bA = p4[1];               // bp_h2[0..3]
            float4 bB = p4[2];               // bp_h2[4..7]
            float dx = ox - cw.x;
            float dy = oy - cw.y;
            float dz = oz - cw.z;
            float d2 = fmaf(dx, dx, fmaf(dy, dy, dz * dz));
            __half2 d2h = __float2half2_rn(d2);      // one F2FP pack
            __half2 wh = *(__half2*)&cw.w;
            const __half2* bpA = (const __half2*)&bA;
            const __half2* bpB = (const __half2*)&bB;
#pragma unroll
            for (int q = 0; q < 4; q++) {
                __half2 arg = __hmul2(bpA[q], d2h);        // HMUL2 (fma pipe)
                unsigned eu = h2ex2_raw(*(unsigned*)&arg); // 1 MUFU, 2 exps
                hacc[q] = __hfma2(*(__half2*)&eu, wh, hacc[q]);
            }
#pragma unroll
            for (int q = 0; q < 4; q++) {
                __half2 arg = __hmul2(bpB[q], d2h);
                unsigned eu = h2ex2_raw(*(unsigned*)&arg);
                hacc[4 + q] = __hfma2(*(__half2*)&eu, wh, hacc[4 + q]);
            }
        }
        // flush to f32
#pragma unroll
        for (int q = 0; q < 8; q++) {
            float2 f = __half22float2(hacc[q]);
            acc[2 * q + 0] += f.x;
            acc[2 * q + 1] += f.y;
        }
    }

    float* outp = g_partial + ((size_t)split * MPTS + i) * NB;
#pragma unroll
    for (int b = 0; b < NB; b++) outp[b] = acc[b];
}

// Vectorized reduce: one thread per 4 outputs, float4 loads across splits.
__global__ void reduce_kernel(float4* __restrict__ out4) {
    int t = blockIdx.x * blockDim.x + threadIdx.x;   // 0 .. MPTS*NB/4-1
    if (t >= MPTS * NB / 4) return;
    float4 s = make_float4(0.0f, 0.0f, 0.0f, 0.0f);
    const float4* part4 = (const float4*)g_partial;
    const int stride = MPTS * NB / 4;
#pragma unroll
    for (int sp = 0; sp < NSPLIT; sp++) {
        float4 v = part4[(size_t)sp * stride + t];
        s.x += v.x; s.y += v.y; s.z += v.z; s.w += v.w;
    }
    float4 hg = ((const float4*)g_heg)[t & 3];   // 4 consecutive channels
    s.x *= hg.x; s.y *= hg.y; s.z *= hg.z; s.w *= hg.w;
    out4[t] = s;
}

extern "C" void kernel_launch(void* const* d_in, const int* in_sizes, int n_in,
                              void* d_out, int out_size) {
    const float* rho        = (const float*)d_in[0];
    const float* gamma      = (const float*)d_in[1];
    const float* coords     = (const float*)d_in[2];
    const float* weights    = (const float*)d_in[3];
    const float* out_coords = (const float*)d_in[4];
    const float* w1         = (const float*)d_in[5];
    const float* b1         = (const float*)d_in[6];
    const float* w2         = (const float*)d_in[7];
    const float* b2         = (const float*)d_in[8];

    setup_kernel<<<NPTS / 8, 256>>>(rho, gamma, coords, weights,
                                    w1, b1, w2, b2);
    dim3 grid(MPTS / IBLK, NSPLIT);
    main_kernel<<<grid, IBLK>>>(out_coords);
    reduce_kernel<<<(MPTS * NB / 4 + 255) / 256, 256>>>((float4*)d_out);
}

// round 17
// speedup vs baseline: 1.0081x; 1.0020x over previous
#include <cuda_runtime.h>
#include <cuda_fp16.h>
#include <math.h>

#define NPTS   8192
#define MPTS   8192
#define NB     16
#define WIDTH  32
#define NSPLIT 19
#define MAXJ   432   // ceil(8192/19) = 432 = 27*16 exactly
#define IBLK   256
#define REC    12    // x, y, z, w_h2(u32), bp_h2[8](u32)

__device__ float g_packed[NPTS * REC];
__device__ __align__(16) float g_heg[NB];
__device__ float g_partial[(size_t)NSPLIT * MPTS * NB];

// ---- raw MUFU helpers ----
__device__ __forceinline__ float f_ex2(float x) {
    float r; asm("ex2.approx.f32 %0, %1;" : "=f"(r) : "f"(x)); return r;
}
__device__ __forceinline__ float f_lg2(float x) {
    float r; asm("lg2.approx.f32 %0, %1;" : "=f"(r) : "f"(x)); return r;
}
__device__ __forceinline__ float f_rcp(float x) {
    float r; asm("rcp.approx.f32 %0, %1;" : "=f"(r) : "f"(x)); return r;
}
__device__ __forceinline__ float fast_tanh(float a) {
    float u = f_ex2(2.885390081777927f * a);   // exp(2a)
    return fmaf(-2.0f, f_rcp(u + 1.0f), 1.0f);
}
__device__ __forceinline__ float fast_log_cosh(float t) {
    const float LN2 = 0.69314718055994531f;
    float a = fabsf(t);
    float v = f_ex2(-2.885390081777927f * a);  // exp(-2a)
    return fmaf(f_lg2(1.0f + v), LN2, a - LN2);
}

// Guaranteed single-op f16x2 exp2 on MUFU (two values per MUFU slot).
__device__ __forceinline__ unsigned h2ex2_raw(unsigned x) {
    unsigned r;
    asm("ex2.approx.f16x2 %0, %1;" : "=r"(r) : "r"(x));
    return r;
}

// Warp-per-point setup (PPW=1: 8192 warps of TLP beats per-warp ILP —
// measured R14 vs R15). Lane k owns hidden unit k; WIDTH->NB via 32 SHFL
// broadcasts (2 accumulators halve the serial chain); lane b<16 owns basis b.
__global__ void __launch_bounds__(256)
setup_kernel(const float* __restrict__ rho,
             const float* __restrict__ gamma,
             const float* __restrict__ coords,
             const float* __restrict__ weights,
             const float* __restrict__ w1,
             const float* __restrict__ b1,
             const float* __restrict__ w2,
             const float* __restrict__ b2) {
    __shared__ float s_w2[WIDTH * NB];
    int tid = threadIdx.x;
    for (int v = tid; v < WIDTH * NB; v += blockDim.x) s_w2[v] = w2[v];
    __syncthreads();

    int lane = tid & 31;
    int warp = tid >> 5;
    int j = blockIdx.x * (blockDim.x >> 5) + warp;
    if (j >= NPTS) return;

    const float C     = 38.283120002509214f;   // 4*(3*pi^2)^(2/3)
    const float LOG2E = 1.44269504088896340f;
    const float LN2   = 0.69314718055994531f;

    float r = rho[j];
    float l = f_lg2(r);
    float r83 = r * r * f_ex2(l * (2.0f / 3.0f));          // r^(8/3)
    float s2 = gamma[j] * f_rcp(C * r83);
    float x = f_lg2(s2 + 1e-4f) * LN2;                     // log(s2+eps)

    float h = fast_tanh(fmaf(x, w1[lane], b1[lane]));

    int bl = lane & (NB - 1);
    float o0 = b2[bl], o1 = 0.0f;
#pragma unroll
    for (int k = 0; k < WIDTH; k += 2) {
        float hk0 = __shfl_sync(0xffffffffu, h, k);
        float hk1 = __shfl_sync(0xffffffffu, h, k + 1);
        o0 = fmaf(hk0, s_w2[k * NB + bl], o0);
        o1 = fmaf(hk1, s_w2[(k + 1) * NB + bl], o1);
    }
    float o = o0 + o1;

    float pref = 3.14159265358979323846f * f_ex2((l - 1.0f) * (2.0f / 3.0f));
    float bp = -pref * fast_log_cosh(o) * LOG2E;

    // pack channel pairs (2q, 2q+1) into half2
    float bpn = __shfl_down_sync(0xffffffffu, bp, 1);
    if (lane < NB && (lane & 1) == 0) {
        __half2 hh = __floats2half2_rn(bp, bpn);
        ((unsigned*)g_packed)[j * REC + 4 + (lane >> 1)] = *(unsigned*)&hh;
    }
    if (lane == 16) g_packed[j * REC + 0] = coords[j * 3 + 0];
    if (lane == 17) g_packed[j * REC + 1] = coords[j * 3 + 1];
    if (lane == 18) g_packed[j * REC + 2] = coords[j * 3 + 2];
    if (lane == 19) {
        __half2 wh = __float2half2_rn(weights[j] * r);
        ((unsigned*)g_packed)[j * REC + 3] = *(unsigned*)&wh;
    }

    if (j == 0) {
        float h0 = fast_tanh(b1[lane]);
        float q0 = b2[bl];
#pragma unroll
        for (int k = 0; k < WIDTH; k++) {
            float hk = __shfl_sync(0xffffffffu, h0, k);
            q0 = fmaf(hk, s_w2[k * NB + bl], q0);
        }
        if (lane < NB) {
            float lc = fast_log_cosh(q0);
            g_heg[lane] = lc * sqrtf(lc);                  // lc^1.5
        }
    }
}

// Grid (32, 19) = 608 blocks = 152 SMs x 4: perfectly balanced on GB300
// (152 = 8*19 forces NSPLIT=19 for balance). Tile zero-padded to exactly
// MAXJ=432=27*16 records: constant trip counts, branch-free body.
// Zero records contribute exactly +0 (w=0), so padding is bit-identical.
__global__ void __launch_bounds__(IBLK)
main_kernel(const float* __restrict__ out_coords) {
    __shared__ float tile[MAXJ * REC];   // 20.7 KB

    int i = blockIdx.x * IBLK + threadIdx.x;
    int split = blockIdx.y;

    float ox = out_coords[i * 3 + 0];
    float oy = out_coords[i * 3 + 1];
    float oz = out_coords[i * 3 + 2];

    int jbeg = (split * NPTS) / NSPLIT;
    int jend = ((split + 1) * NPTS) / NSPLIT;
    int cnt = jend - jbeg;

    {
        const float4* src = (const float4*)(g_packed + (size_t)jbeg * REC);
        float4* dst = (float4*)tile;
        int nvec = cnt * (REC / 4);            // 3 float4 per j
        const int nvec_pad = MAXJ * (REC / 4); // fill remainder with zeros
        for (int v = threadIdx.x; v < nvec_pad; v += IBLK)
            dst[v] = (v < nvec) ? src[v]
                                : make_float4(0.0f, 0.0f, 0.0f, 0.0f);
    }
    __syncthreads();

    float acc[NB];
#pragma unroll
    for (int b = 0; b < NB; b++) acc[b] = 0.0f;

#pragma unroll 1
    for (int j0 = 0; j0 < MAXJ; j0 += 16) {
        // half2 partial accumulators (16 terms, each <=0.2: no overflow)
        __half2 hacc[8];
#pragma unroll
        for (int q = 0; q < 8; q++) hacc[q] = __float2half2_rn(0.0f);

#pragma unroll
        for (int jt = j0; jt < j0 + 16; ++jt) {
            const float* p = tile + jt * REC;
            float4 cw = *(const float4*)p;   // x, y, z, w_h2(bits)
            float dx = ox - cw.x;
            float dy = oy - cw.y;
            float dz = oz - cw.z;
            float d2 = fmaf(dx, dx, fmaf(dy, dy, dz * dz));
            __half2 d2h = __float2half2_rn(d2);      // one F2FP pack
            __half2 wh = *(__half2*)&cw.w;
            const __half2* bp = (const __half2*)(p + 4);
#pragma unroll
            for (int q = 0; q < 8; q++) {
                __half2 arg = __hmul2(bp[q], d2h);   // HMUL2 (fma pipe)
                unsigned eu = h2ex2_raw(*(unsigned*)&arg); // 1 MUFU, 2 exps
                hacc[q] = __hfma2(*(__half2*)&eu, wh, hacc[q]);
            }
        }
        // flush to f32
#pragma unroll
        for (int q = 0; q < 8; q++) {
            float2 f = __half22float2(hacc[q]);
            acc[2 * q + 0] += f.x;
            acc[2 * q + 1] += f.y;
        }
    }

    float* outp = g_partial + ((size_t)split * MPTS + i) * NB;
#pragma unroll
    for (int b = 0; b < NB; b++) outp[b] = acc[b];
}

// Vectorized reduce: one thread per 4 outputs, float4 loads across splits.
__global__ void reduce_kernel(float4* __restrict__ out4) {
    int t = blockIdx.x * blockDim.x + threadIdx.x;   // 0 .. MPTS*NB/4-1
    if (t >= MPTS * NB / 4) return;
    float4 s = make_float4(0.0f, 0.0f, 0.0f, 0.0f);
    const float4* part4 = (const float4*)g_partial;
    const int stride = MPTS * NB / 4;
#pragma unroll
    for (int sp = 0; sp < NSPLIT; sp++) {
        float4 v = part4[(size_t)sp * stride + t];
        s.x += v.x; s.y += v.y; s.z += v.z; s.w += v.w;
    }
    float4 hg = ((const float4*)g_heg)[t & 3];   // 4 consecutive channels
    s.x *= hg.x; s.y *= hg.y; s.z *= hg.z; s.w *= hg.w;
    out4[t] = s;
}

extern "C" void kernel_launch(void* const* d_in, const int* in_sizes, int n_in,
                              void* d_out, int out_size) {
    const float* rho        = (const float*)d_in[0];
    const float* gamma      = (const float*)d_in[1];
    const float* coords     = (const float*)d_in[2];
    const float* weights    = (const float*)d_in[3];
    const float* out_coords = (const float*)d_in[4];
    const float* w1         = (const float*)d_in[5];
    const float* b1         = (const float*)d_in[6];
    const float* w2         = (const float*)d_in[7];
    const float* b2         = (const float*)d_in[8];

    setup_kernel<<<NPTS / 8, 256>>>(rho, gamma, coords, weights,
                                    w1, b1, w2, b2);
    dim3 grid(MPTS / IBLK, NSPLIT);
    main_kernel<<<grid, IBLK>>>(out_coords);
    reduce_kernel<<<(MPTS * NB / 4 + 255) / 256, 256>>>((float4*)d_out);
}